// round 5
// baseline (speedup 1.0000x reference)
#include <cuda_runtime.h>
#include <cuda_fp16.h>
#include <math.h>
#include <stdint.h>

#define BB 4
#define NN 1024
#define DD 1024
#define HH 16
#define DKK 64

// ---------------- scratch (allocation-free) ----------------
__device__ __half g_xh[(size_t)BB*NN*DD];
__device__ __half g_xl[(size_t)BB*NN*DD];
__device__ __half g_wh[4*(size_t)DD*DD];
__device__ __half g_qh[(size_t)BB*HH*NN*DKK];
__device__ __half g_kh[(size_t)BB*HH*NN*DKK];
__device__ __half g_vh[(size_t)BB*HH*NN*DKK];
__device__ __half g_ah[(size_t)BB*NN*DD];
__device__ __half g_al[(size_t)BB*NN*DD];

// ---------------- fp16 mma m16n8k16 ----------------
__device__ __forceinline__ void mma16(float* d, const uint32_t* a, uint32_t b0, uint32_t b1) {
    asm volatile(
        "mma.sync.aligned.m16n8k16.row.col.f32.f16.f16.f32 "
        "{%0,%1,%2,%3},{%4,%5,%6,%7},{%8,%9},{%0,%1,%2,%3};"
        : "+f"(d[0]), "+f"(d[1]), "+f"(d[2]), "+f"(d[3])
        : "r"(a[0]), "r"(a[1]), "r"(a[2]), "r"(a[3]), "r"(b0), "r"(b1));
}

// ---------------- cvt kernels ----------------
__global__ void cvt_hl(const float* __restrict__ s, __half* __restrict__ h,
                       __half* __restrict__ l, int n) {
    for (int i = blockIdx.x * blockDim.x + threadIdx.x; i < n; i += gridDim.x * blockDim.x) {
        float v = s[i];
        __half hv = __float2half_rn(v);
        h[i] = hv;
        l[i] = __float2half_rn(v - __half2float(hv));
    }
}
__global__ void cvt_h(const float* __restrict__ s, __half* __restrict__ h, int n) {
    for (int i = blockIdx.x * blockDim.x + threadIdx.x; i < n; i += gridDim.x * blockDim.x)
        h[i] = __float2half_rn(s[i]);
}

// ---------------------------------------------------------------------------
// fp16 A-compensated GEMM: C[m,e] = sum_d (Ah+Al)[m,d]*W[e,d] + bias[e]
// Two mma passes (AhW, AlW) into the same fp32 accumulator.
// Block tile 128x128, k-slab 32, 8 warps (warp tile 32x64).
// MODE 0/1/2: write half to g_qh/g_kh/g_vh [b][h][n][dk]. MODE 3: fp32 dst.
// ---------------------------------------------------------------------------
template<int MODE>
__global__ __launch_bounds__(256) void gemm_hp(
    const __half* __restrict__ Ah, const __half* __restrict__ Al,
    const __half* __restrict__ W,
    const float* __restrict__ bias, float* __restrict__ dst)
{
    __shared__ __half Ahs[128][40];
    __shared__ __half Als[128][40];
    __shared__ __half Wss[128][40];

    const int t = threadIdx.x, lane = t & 31, w = t >> 5;
    const int wm = w & 3, wn = w >> 2;
    const int g = lane >> 2, q4 = lane & 3;
    const int m0 = blockIdx.x * 128, e0 = blockIdx.y * 128;

    float c[2][8][4] = {};

    for (int k0 = 0; k0 < DD; k0 += 32) {
        #pragma unroll
        for (int i = 0; i < 2; i++) {
            const int id = t + 256 * i;          // 0..511
            const int r = id >> 2, cc = (id & 3) * 8;
            *(uint4*)&Ahs[r][cc] = *(const uint4*)(Ah + (size_t)(m0 + r)*DD + k0 + cc);
            *(uint4*)&Als[r][cc] = *(const uint4*)(Al + (size_t)(m0 + r)*DD + k0 + cc);
            *(uint4*)&Wss[r][cc] = *(const uint4*)(W  + (size_t)(e0 + r)*DD + k0 + cc);
        }
        __syncthreads();

        #pragma unroll
        for (int ks = 0; ks < 2; ks++) {          // two k16 steps
            const int kc = ks*16 + 2*q4;
            uint32_t ah[2][4], al[2][4];
            #pragma unroll
            for (int mt = 0; mt < 2; mt++) {
                const int row = wm*32 + mt*16;
                ah[mt][0] = *(const uint32_t*)&Ahs[row + g    ][kc];
                ah[mt][1] = *(const uint32_t*)&Ahs[row + g + 8][kc];
                ah[mt][2] = *(const uint32_t*)&Ahs[row + g    ][kc + 8];
                ah[mt][3] = *(const uint32_t*)&Ahs[row + g + 8][kc + 8];
                al[mt][0] = *(const uint32_t*)&Als[row + g    ][kc];
                al[mt][1] = *(const uint32_t*)&Als[row + g + 8][kc];
                al[mt][2] = *(const uint32_t*)&Als[row + g    ][kc + 8];
                al[mt][3] = *(const uint32_t*)&Als[row + g + 8][kc + 8];
            }
            #pragma unroll
            for (int nt = 0; nt < 8; nt++) {
                const int br = wn*64 + nt*8 + g;
                const uint32_t b0 = *(const uint32_t*)&Wss[br][kc];
                const uint32_t b1 = *(const uint32_t*)&Wss[br][kc + 8];
                mma16(c[0][nt], ah[0], b0, b1);
                mma16(c[1][nt], ah[1], b0, b1);
                mma16(c[0][nt], al[0], b0, b1);
                mma16(c[1][nt], al[1], b0, b1);
            }
        }
        __syncthreads();
    }

    // epilogue
    #pragma unroll
    for (int mt = 0; mt < 2; mt++) {
        #pragma unroll
        for (int rr = 0; rr < 2; rr++) {
            const int m = m0 + wm*32 + mt*16 + g + rr*8;
            const int b = m >> 10, n = m & 1023;
            #pragma unroll
            for (int nt = 0; nt < 8; nt++) {
                const int e = e0 + wn*64 + nt*8 + 2*q4;
                const float v0 = c[mt][nt][rr*2 + 0] + bias[e];
                const float v1 = c[mt][nt][rr*2 + 1] + bias[e + 1];
                if (MODE == 3) {
                    float2 v; v.x = v0; v.y = v1;
                    *(float2*)(dst + (size_t)m*DD + e) = v;
                } else {
                    __half* gp = (MODE == 0) ? g_qh : (MODE == 1) ? g_kh : g_vh;
                    __half2 hv = __floats2half2_rn(v0, v1);
                    *(uint32_t*)(gp + (((size_t)(b*HH + (e >> 6)))*NN + n)*DKK + (e & 63)) =
                        *(uint32_t*)&hv;
                }
            }
        }
    }
}

// ---------------------------------------------------------------------------
// Flash attention, fp16 m16n8k16. Block = (b,h,128 queries), 8 warps (m16).
// Q fragments register-resident; P stays in registers (C->A frag identity).
// KV tile 64; fully-masked tiles skipped. Output -> hi/lo halves for O-proj.
// ---------------------------------------------------------------------------
#define KS_STRIDE 72   // halves

__global__ __launch_bounds__(256) void attn_fwd(const void* __restrict__ maskp)
{
    __shared__ __half Ks[64 * KS_STRIDE];
    __shared__ __half Vt[64 * KS_STRIDE];   // transposed: [dk][kv]

    const int b = blockIdx.z, h = blockIdx.y, q0 = blockIdx.x * 128;
    const __half* K = g_kh + (size_t)(b*HH + h) * NN * DKK;
    const __half* V = g_vh + (size_t)(b*HH + h) * NN * DKK;

    // mask element-width probe (u8 bool vs 4-byte dtype)
    const int probe = *(const int*)((const char*)maskp + (BB*NN - 4));
    const bool mu8 = (probe == 0x01010101);
    const unsigned char* m8  = (const unsigned char*)maskp + b*NN;
    const unsigned int*  m32 = (const unsigned int*)maskp + b*NN;

    const int t = threadIdx.x, lane = t & 31, w = t >> 5;
    const int g = lane >> 2, q4 = lane & 3;

    // preload Q fragments (4 k-chunks x 4 regs)
    uint32_t qa[4][4];
    {
        const __half* Q = g_qh + ((size_t)(b*HH + h) * NN + q0 + w*16) * DKK;
        #pragma unroll
        for (int kc = 0; kc < 4; kc++) {
            const int c = 16*kc + 2*q4;
            qa[kc][0] = *(const uint32_t*)(Q + (size_t)g      * DKK + c);
            qa[kc][1] = *(const uint32_t*)(Q + (size_t)(g + 8)* DKK + c);
            qa[kc][2] = *(const uint32_t*)(Q + (size_t)g      * DKK + c + 8);
            qa[kc][3] = *(const uint32_t*)(Q + (size_t)(g + 8)* DKK + c + 8);
        }
    }

    float o[8][4] = {};
    float mrow[2] = {-INFINITY, -INFINITY};
    float lrow[2] = {0.f, 0.f};
    const float scale = 0.125f;   // 1/sqrt(64)

    for (int kv0 = 0; kv0 < NN; kv0 += 64) {
        // skip fully-masked tiles; doubles as the cross-iteration barrier
        const int key = kv0 + (t & 63);
        const int mp = mu8 ? (m8[key] != 0) : (m32[key] != 0);
        if (__syncthreads_and(mp)) continue;

        // load K tile [kv][dk] and V transposed [dk][kv]
        #pragma unroll
        for (int i = 0; i < 4; i++) {
            const int id = t + 256*i;
            const int r = id >> 4, c4 = (id & 15) * 4;
            *(uint2*)&Ks[r*KS_STRIDE + c4] = *(const uint2*)(K + (size_t)(kv0 + r)*DKK + c4);
            uint2 vv = *(const uint2*)(V + (size_t)(kv0 + r)*DKK + c4);
            const __half* vh = (const __half*)&vv;
            Vt[(c4+0)*KS_STRIDE + r] = vh[0];
            Vt[(c4+1)*KS_STRIDE + r] = vh[1];
            Vt[(c4+2)*KS_STRIDE + r] = vh[2];
            Vt[(c4+3)*KS_STRIDE + r] = vh[3];
        }
        __syncthreads();

        // S = Q K^T : m16 x n64 x k64
        float s[8][4] = {};
        #pragma unroll
        for (int nt = 0; nt < 8; nt++) {
            #pragma unroll
            for (int kc = 0; kc < 4; kc++) {
                const uint32_t b0 = *(const uint32_t*)&Ks[(8*nt + g)*KS_STRIDE + 16*kc + 2*q4];
                const uint32_t b1 = *(const uint32_t*)&Ks[(8*nt + g)*KS_STRIDE + 16*kc + 2*q4 + 8];
                mma16(s[nt], qa[kc], b0, b1);
            }
        }

        // scale + key padding mask
        #pragma unroll
        for (int nt = 0; nt < 8; nt++) {
            const int kc0 = kv0 + 8*nt + 2*q4;
            const bool mk0 = mu8 ? (m8[kc0] != 0)   : (m32[kc0] != 0);
            const bool mk1 = mu8 ? (m8[kc0+1] != 0) : (m32[kc0+1] != 0);
            s[nt][0] = mk0 ? -3.0e38f : s[nt][0] * scale;
            s[nt][1] = mk1 ? -3.0e38f : s[nt][1] * scale;
            s[nt][2] = mk0 ? -3.0e38f : s[nt][2] * scale;
            s[nt][3] = mk1 ? -3.0e38f : s[nt][3] * scale;
        }

        // online softmax; build P fragments directly in registers
        uint32_t ph[8][2];
        #pragma unroll
        for (int rr = 0; rr < 2; rr++) {
            float tm = -INFINITY;
            #pragma unroll
            for (int nt = 0; nt < 8; nt++)
                tm = fmaxf(tm, fmaxf(s[nt][rr*2], s[nt][rr*2+1]));
            tm = fmaxf(tm, __shfl_xor_sync(0xffffffffu, tm, 1));
            tm = fmaxf(tm, __shfl_xor_sync(0xffffffffu, tm, 2));
            const float mnew = fmaxf(mrow[rr], tm);
            const float alpha = __expf(mrow[rr] - mnew);
            mrow[rr] = mnew;
            float ps = 0.f;
            #pragma unroll
            for (int nt = 0; nt < 8; nt++) {
                const float p0 = __expf(s[nt][rr*2]   - mnew);
                const float p1 = __expf(s[nt][rr*2+1] - mnew);
                ps += p0 + p1;
                __half2 hp = __floats2half2_rn(p0, p1);
                ph[nt][rr] = *(uint32_t*)&hp;
            }
            ps += __shfl_xor_sync(0xffffffffu, ps, 1);
            ps += __shfl_xor_sync(0xffffffffu, ps, 2);
            lrow[rr] = lrow[rr] * alpha + ps;
            #pragma unroll
            for (int nt = 0; nt < 8; nt++) {
                o[nt][rr*2]   *= alpha;
                o[nt][rr*2+1] *= alpha;
            }
        }

        // O += P V : S C-fragments reinterpreted as PV A-fragments
        #pragma unroll
        for (int kc = 0; kc < 4; kc++) {
            uint32_t pa[4];
            pa[0] = ph[2*kc][0];   pa[1] = ph[2*kc][1];
            pa[2] = ph[2*kc+1][0]; pa[3] = ph[2*kc+1][1];
            #pragma unroll
            for (int nt = 0; nt < 8; nt++) {
                const uint32_t b0 = *(const uint32_t*)&Vt[(8*nt + g)*KS_STRIDE + 16*kc + 2*q4];
                const uint32_t b1 = *(const uint32_t*)&Vt[(8*nt + g)*KS_STRIDE + 16*kc + 2*q4 + 8];
                mma16(o[nt], pa, b0, b1);
            }
        }
    }

    // epilogue: hi/lo halves for the compensated O-projection
    #pragma unroll
    for (int rr = 0; rr < 2; rr++) {
        const float inv = 1.0f / lrow[rr];
        const int n = q0 + w*16 + g + rr*8;
        #pragma unroll
        for (int nt = 0; nt < 8; nt++) {
            const float f0 = o[nt][rr*2]   * inv;
            const float f1 = o[nt][rr*2+1] * inv;
            const __half h0 = __float2half_rn(f0), h1 = __float2half_rn(f1);
            const __half l0 = __float2half_rn(f0 - __half2float(h0));
            const __half l1 = __float2half_rn(f1 - __half2float(h1));
            const size_t idx = ((size_t)b*NN + n)*DD + h*DKK + 8*nt + 2*q4;
            __half2 hh = __halves2half2(h0, h1), ll = __halves2half2(l0, l1);
            *(uint32_t*)(g_ah + idx) = *(uint32_t*)&hh;
            *(uint32_t*)(g_al + idx) = *(uint32_t*)&ll;
        }
    }
}

// ---------------------------------------------------------------------------
extern "C" void kernel_launch(void* const* d_in, const int* in_sizes, int n_in,
                              void* d_out, int out_size)
{
    const float* x    = (const float*)d_in[0];
    const void*  mask = d_in[1];
    const float* Wq   = (const float*)d_in[2];
    const float* bq   = (const float*)d_in[3];
    const float* Wk   = (const float*)d_in[4];
    const float* bk   = (const float*)d_in[5];
    const float* Wv   = (const float*)d_in[6];
    const float* bv   = (const float*)d_in[7];
    const float* Wo   = (const float*)d_in[8];
    const float* bo   = (const float*)d_in[9];
    float* out = (float*)d_out;

    __half *xh, *xl, *wh, *ah, *al;
    cudaGetSymbolAddress((void**)&xh, g_xh);
    cudaGetSymbolAddress((void**)&xl, g_xl);
    cudaGetSymbolAddress((void**)&wh, g_wh);
    cudaGetSymbolAddress((void**)&ah, g_ah);
    cudaGetSymbolAddress((void**)&al, g_al);

    // hi/lo decomposition of x; weights to fp16 (hi only)
    cvt_hl<<<512, 256>>>(x,  xh, xl, BB*NN*DD);
    cvt_h<<<256, 256>>>(Wq, wh + 0*(size_t)DD*DD, DD*DD);
    cvt_h<<<256, 256>>>(Wk, wh + 1*(size_t)DD*DD, DD*DD);
    cvt_h<<<256, 256>>>(Wv, wh + 2*(size_t)DD*DD, DD*DD);
    cvt_h<<<256, 256>>>(Wo, wh + 3*(size_t)DD*DD, DD*DD);

    dim3 ggrid(BB*NN/128, DD/128);   // 32 x 8
    gemm_hp<0><<<ggrid, 256>>>(xh, xl, wh + 0*(size_t)DD*DD, bq, nullptr);
    gemm_hp<1><<<ggrid, 256>>>(xh, xl, wh + 1*(size_t)DD*DD, bk, nullptr);
    gemm_hp<2><<<ggrid, 256>>>(xh, xl, wh + 2*(size_t)DD*DD, bv, nullptr);

    dim3 agrid(NN/128, HH, BB);      // 8 x 16 x 4
    attn_fwd<<<agrid, 256>>>(mask);

    gemm_hp<3><<<ggrid, 256>>>(ah, al, wh + 3*(size_t)DD*DD, bo, out);
}

// round 6
// speedup vs baseline: 2.6892x; 2.6892x over previous
#include <cuda_runtime.h>
#include <cuda_fp16.h>
#include <math.h>
#include <stdint.h>

#define BB 4
#define NN 1024
#define DD 1024
#define HH 16
#define DKK 64

// ---------------- scratch (allocation-free) ----------------
__device__ __half g_xh[(size_t)BB*NN*DD];
__device__ __half g_wh[4*(size_t)DD*DD];
__device__ __half g_qh[(size_t)BB*HH*NN*DKK];
__device__ __half g_kh[(size_t)BB*HH*NN*DKK];
__device__ __half g_vh[(size_t)BB*HH*NN*DKK];
__device__ __half g_ah[(size_t)BB*NN*DD];

// ---------------- helpers ----------------
__device__ __forceinline__ uint32_t smem_u32(const void* p) {
    uint32_t a;
    asm("{ .reg .u64 t; cvta.to.shared.u64 t, %1; cvt.u32.u64 %0, t; }" : "=r"(a) : "l"(p));
    return a;
}
__device__ __forceinline__ void mma16(float* d, const uint32_t* a, uint32_t b0, uint32_t b1) {
    asm volatile(
        "mma.sync.aligned.m16n8k16.row.col.f32.f16.f16.f32 "
        "{%0,%1,%2,%3},{%4,%5,%6,%7},{%8,%9},{%0,%1,%2,%3};"
        : "+f"(d[0]), "+f"(d[1]), "+f"(d[2]), "+f"(d[3])
        : "r"(a[0]), "r"(a[1]), "r"(a[2]), "r"(a[3]), "r"(b0), "r"(b1));
}
__device__ __forceinline__ void ldsm_x4(uint32_t* r, uint32_t a) {
    asm volatile("ldmatrix.sync.aligned.m8n8.x4.shared.b16 {%0,%1,%2,%3}, [%4];"
        : "=r"(r[0]), "=r"(r[1]), "=r"(r[2]), "=r"(r[3]) : "r"(a));
}
__device__ __forceinline__ void ldsm_x4_t(uint32_t* r, uint32_t a) {
    asm volatile("ldmatrix.sync.aligned.m8n8.x4.trans.shared.b16 {%0,%1,%2,%3}, [%4];"
        : "=r"(r[0]), "=r"(r[1]), "=r"(r[2]), "=r"(r[3]) : "r"(a));
}
#define CP_ASYNC16(dst, src) \
    asm volatile("cp.async.cg.shared.global [%0], [%1], 16;" :: "r"(dst), "l"(src))
#define CP_COMMIT() asm volatile("cp.async.commit_group;")
#define CP_WAIT1() asm volatile("cp.async.wait_group 1;")
#define CP_WAIT0() asm volatile("cp.async.wait_group 0;")

// ---------------- fused cvt: x + all 4 W -> fp16 ----------------
__global__ __launch_bounds__(256) void cvt_all(
    const float4* __restrict__ x, const float4* __restrict__ wq,
    const float4* __restrict__ wk, const float4* __restrict__ wv,
    const float4* __restrict__ wo)
{
    const int n4x = (BB*NN*DD)/4;     // 1M
    const int n4w = (DD*DD)/4;        // 256K
    const int total = n4x + 4*n4w;
    for (int i = blockIdx.x*blockDim.x + threadIdx.x; i < total; i += gridDim.x*blockDim.x) {
        const float4* src; __half2* dst; int off;
        if (i < n4x) { src = x; off = i; dst = (__half2*)g_xh; }
        else {
            int j = i - n4x; int r = j / n4w; off = j - r*n4w;
            src = (r == 0) ? wq : (r == 1) ? wk : (r == 2) ? wv : wo;
            dst = (__half2*)(g_wh + (size_t)r*DD*DD);
        }
        float4 v = src[off];
        dst[off*2]   = __floats2half2_rn(v.x, v.y);
        dst[off*2+1] = __floats2half2_rn(v.z, v.w);
    }
}

// ---------------------------------------------------------------------------
// fp16 GEMM: C[m,e] = sum_d A[m,d]*W[e,d] + bias[e]
// 128x128 tile, k-slab 64, cp.async double-buffered, ldmatrix fragments.
// MODE 0/1/2: write half to g_qh/g_kh/g_vh [b][h][n][dk]. MODE 3: fp32 dst.
// ---------------------------------------------------------------------------
#define STAGE_B 32768   // A tile 16KB + B tile 16KB
#define G_SMEM  (2*STAGE_B)

template<int MODE>
__global__ __launch_bounds__(256, 2) void gemm_hp(
    const __half* __restrict__ A, const __half* __restrict__ W,
    const float* __restrict__ bias, float* __restrict__ dst)
{
    extern __shared__ __align__(128) char sm[];
    const uint32_t sb = smem_u32(sm);
    const int t = threadIdx.x, lane = t & 31, w = t >> 5;
    const int wm = w & 3, wn = w >> 2;
    const int g = lane >> 2, q4 = lane & 3;
    const int m0 = blockIdx.x * 128, e0 = blockIdx.y * 128;

    float c[2][8][4] = {};

    // issue cp.async loads of slab -> stage
    auto load_slab = [&](int slab, int stage) {
        const int k0 = slab * 64;
        const uint32_t base = sb + stage * STAGE_B;
        #pragma unroll
        for (int i = 0; i < 8; i++) {
            const int id = t + 256*i;                 // 0..2047
            const int isB = id >> 10;                 // first 1024 = A
            const int lid = id & 1023;
            const int r = lid >> 3, cc = lid & 7;     // row, 16B chunk
            const uint32_t so = base + isB*16384 + r*128 + ((cc ^ (r & 7)) << 4);
            const __half* gp = isB ? (W + (size_t)(e0 + r)*DD + k0 + cc*8)
                                   : (A + (size_t)(m0 + r)*DD + k0 + cc*8);
            CP_ASYNC16(so, gp);
        }
        CP_COMMIT();
    };

    load_slab(0, 0);
    load_slab(1, 1);

    for (int slab = 0; slab < 16; slab++) {
        if (slab == 15) { CP_WAIT0(); } else { CP_WAIT1(); }
        __syncthreads();

        const uint32_t aBase = sb + (slab & 1) * STAGE_B;
        const uint32_t bBase = aBase + 16384;

        #pragma unroll
        for (int ks = 0; ks < 4; ks++) {
            uint32_t a[2][4];
            #pragma unroll
            for (int mt = 0; mt < 2; mt++) {
                const int row = wm*32 + mt*16 + (lane & 15);
                const int cc = ks*2 + (lane >> 4);
                ldsm_x4(a[mt], aBase + row*128 + ((cc ^ (row & 7)) << 4));
            }
            uint32_t bf[8][2];
            #pragma unroll
            for (int np = 0; np < 4; np++) {
                const int row = wn*64 + np*16 + (lane & 7) + ((lane >> 4) << 3);
                const int cc = ks*2 + ((lane >> 3) & 1);
                uint32_t r4[4];
                ldsm_x4(r4, bBase + row*128 + ((cc ^ (row & 7)) << 4));
                bf[2*np][0] = r4[0]; bf[2*np][1] = r4[1];
                bf[2*np+1][0] = r4[2]; bf[2*np+1][1] = r4[3];
            }
            #pragma unroll
            for (int nt = 0; nt < 8; nt++) {
                mma16(c[0][nt], a[0], bf[nt][0], bf[nt][1]);
                mma16(c[1][nt], a[1], bf[nt][0], bf[nt][1]);
            }
        }
        __syncthreads();
        if (slab + 2 < 16) load_slab(slab + 2, slab & 1);
    }

    // epilogue
    #pragma unroll
    for (int mt = 0; mt < 2; mt++) {
        #pragma unroll
        for (int rr = 0; rr < 2; rr++) {
            const int m = m0 + wm*32 + mt*16 + g + rr*8;
            const int b = m >> 10, n = m & 1023;
            #pragma unroll
            for (int nt = 0; nt < 8; nt++) {
                const int e = e0 + wn*64 + nt*8 + 2*q4;
                const float v0 = c[mt][nt][rr*2 + 0] + bias[e];
                const float v1 = c[mt][nt][rr*2 + 1] + bias[e + 1];
                if (MODE == 3) {
                    float2 v; v.x = v0; v.y = v1;
                    *(float2*)(dst + (size_t)m*DD + e) = v;
                } else {
                    __half* gp = (MODE == 0) ? g_qh : (MODE == 1) ? g_kh : g_vh;
                    __half2 hv = __floats2half2_rn(v0, v1);
                    *(uint32_t*)(gp + (((size_t)(b*HH + (e >> 6)))*NN + n)*DKK + (e & 63)) =
                        *(uint32_t*)&hv;
                }
            }
        }
    }
}

// ---------------------------------------------------------------------------
// Flash attention, fp16 m16n8k16. Block = (b,h,128 queries), 8 warps (m16).
// cp.async double-buffered K/V tiles over precomputed active-tile list.
// K via ldmatrix, V via ldmatrix.trans. P stays in registers.
// ---------------------------------------------------------------------------
__global__ __launch_bounds__(256) void attn_fwd(const void* __restrict__ maskp)
{
    __shared__ __align__(128) char skv[2][16384];   // per stage: K 8KB + V 8KB
    __shared__ int tflag[16], tlist[16], tcount;

    const int b = blockIdx.z, h = blockIdx.y, q0 = blockIdx.x * 128;
    const __half* K = g_kh + (size_t)(b*HH + h) * NN * DKK;
    const __half* V = g_vh + (size_t)(b*HH + h) * NN * DKK;

    // mask element-width probe (u8 bool vs 4-byte dtype)
    const int probe = *(const int*)((const char*)maskp + (BB*NN - 4));
    const bool mu8 = (probe == 0x01010101);
    const unsigned char* m8  = (const unsigned char*)maskp + b*NN;
    const unsigned int*  m32 = (const unsigned int*)maskp + b*NN;

    const int t = threadIdx.x, lane = t & 31, w = t >> 5;
    const int g = lane >> 2, q4 = lane & 3;
    const uint32_t sb = smem_u32(skv);

    // build active-tile list (16 tiles of 64 keys)
    if (t < 16) tflag[t] = 0;
    __syncthreads();
    {
        const int k0 = t * 4;
        bool alive = false;
        #pragma unroll
        for (int j = 0; j < 4; j++)
            alive |= !(mu8 ? (m8[k0+j] != 0) : (m32[k0+j] != 0));
        if (alive) atomicOr(&tflag[t >> 4], 1);
    }
    __syncthreads();
    if (t == 0) {
        int c = 0;
        for (int i = 0; i < 16; i++) if (tflag[i]) tlist[c++] = i;
        tcount = c;
    }
    __syncthreads();
    const int nact = tcount;

    // preload Q fragments (4 k-chunks x 4 regs)
    uint32_t qa[4][4];
    {
        const __half* Q = g_qh + ((size_t)(b*HH + h) * NN + q0 + w*16) * DKK;
        #pragma unroll
        for (int kc = 0; kc < 4; kc++) {
            const int cc = 16*kc + 2*q4;
            qa[kc][0] = *(const uint32_t*)(Q + (size_t)g      * DKK + cc);
            qa[kc][1] = *(const uint32_t*)(Q + (size_t)(g + 8)* DKK + cc);
            qa[kc][2] = *(const uint32_t*)(Q + (size_t)g      * DKK + cc + 8);
            qa[kc][3] = *(const uint32_t*)(Q + (size_t)(g + 8)* DKK + cc + 8);
        }
    }

    auto load_tile = [&](int kt, int stage) {
        const uint32_t base = sb + stage * 16384;
        const __half* Kp = K + (size_t)kt * 64 * DKK;
        const __half* Vp = V + (size_t)kt * 64 * DKK;
        #pragma unroll
        for (int i = 0; i < 4; i++) {
            const int id = t + 256*i;             // 0..1023
            const int isV = id >> 9;              // first 512 = K
            const int lid = id & 511;
            const int r = lid >> 3, cc = lid & 7;
            const uint32_t so = base + isV*8192 + r*128 + ((cc ^ (r & 7)) << 4);
            const __half* gp = (isV ? Vp : Kp) + (size_t)r*DKK + cc*8;
            CP_ASYNC16(so, gp);
        }
        CP_COMMIT();
    };

    load_tile(tlist[0], 0);
    if (nact > 1) load_tile(tlist[1], 1);

    float o[8][4] = {};
    float mrow[2] = {-INFINITY, -INFINITY};
    float lrow[2] = {0.f, 0.f};
    const float scale = 0.125f;   // 1/sqrt(64)

    for (int it = 0; it < nact; it++) {
        if (it == nact - 1) { CP_WAIT0(); } else { CP_WAIT1(); }
        __syncthreads();

        const int kv0 = tlist[it] * 64;
        const uint32_t kBase = sb + (it & 1) * 16384;
        const uint32_t vBase = kBase + 8192;

        // S = Q K^T : m16 x n64 x k64
        float s[8][4] = {};
        #pragma unroll
        for (int kc = 0; kc < 4; kc++) {
            #pragma unroll
            for (int np = 0; np < 4; np++) {
                const int row = np*16 + (lane & 7) + ((lane >> 4) << 3);
                const int cc = kc*2 + ((lane >> 3) & 1);
                uint32_t r4[4];
                ldsm_x4(r4, kBase + row*128 + ((cc ^ (row & 7)) << 4));
                mma16(s[2*np],   qa[kc], r4[0], r4[1]);
                mma16(s[2*np+1], qa[kc], r4[2], r4[3]);
            }
        }

        // scale + key padding mask
        #pragma unroll
        for (int nt = 0; nt < 8; nt++) {
            const int kc0 = kv0 + 8*nt + 2*q4;
            const bool mk0 = mu8 ? (m8[kc0] != 0)   : (m32[kc0] != 0);
            const bool mk1 = mu8 ? (m8[kc0+1] != 0) : (m32[kc0+1] != 0);
            s[nt][0] = mk0 ? -3.0e38f : s[nt][0] * scale;
            s[nt][1] = mk1 ? -3.0e38f : s[nt][1] * scale;
            s[nt][2] = mk0 ? -3.0e38f : s[nt][2] * scale;
            s[nt][3] = mk1 ? -3.0e38f : s[nt][3] * scale;
        }

        // online softmax; P fragments built in registers
        uint32_t ph[8][2];
        #pragma unroll
        for (int rr = 0; rr < 2; rr++) {
            float tm = -INFINITY;
            #pragma unroll
            for (int nt = 0; nt < 8; nt++)
                tm = fmaxf(tm, fmaxf(s[nt][rr*2], s[nt][rr*2+1]));
            tm = fmaxf(tm, __shfl_xor_sync(0xffffffffu, tm, 1));
            tm = fmaxf(tm, __shfl_xor_sync(0xffffffffu, tm, 2));
            const float mnew = fmaxf(mrow[rr], tm);
            const float alpha = __expf(mrow[rr] - mnew);
            mrow[rr] = mnew;
            float ps = 0.f;
            #pragma unroll
            for (int nt = 0; nt < 8; nt++) {
                const float p0 = __expf(s[nt][rr*2]   - mnew);
                const float p1 = __expf(s[nt][rr*2+1] - mnew);
                ps += p0 + p1;
                __half2 hp = __floats2half2_rn(p0, p1);
                ph[nt][rr] = *(uint32_t*)&hp;
            }
            ps += __shfl_xor_sync(0xffffffffu, ps, 1);
            ps += __shfl_xor_sync(0xffffffffu, ps, 2);
            lrow[rr] = lrow[rr] * alpha + ps;
            #pragma unroll
            for (int nt = 0; nt < 8; nt++) {
                o[nt][rr*2]   *= alpha;
                o[nt][rr*2+1] *= alpha;
            }
        }

        // O += P V : V fragments via ldmatrix.trans
        #pragma unroll
        for (int kc = 0; kc < 4; kc++) {
            uint32_t pa[4];
            pa[0] = ph[2*kc][0];   pa[1] = ph[2*kc][1];
            pa[2] = ph[2*kc+1][0]; pa[3] = ph[2*kc+1][1];
            #pragma unroll
            for (int np = 0; np < 4; np++) {
                const int row = 16*kc + (lane & 7) + (((lane >> 3) & 1) << 3);
                const int cc = np*2 + (lane >> 4);
                uint32_t r4[4];
                ldsm_x4_t(r4, vBase + row*128 + ((cc ^ (row & 7)) << 4));
                mma16(o[2*np],   pa, r4[0], r4[1]);
                mma16(o[2*np+1], pa, r4[2], r4[3]);
            }
        }

        __syncthreads();
        if (it + 2 < nact) load_tile(tlist[it + 2], it & 1);
    }

    // epilogue: fp16 attn output for the O-projection
    #pragma unroll
    for (int rr = 0; rr < 2; rr++) {
        const float inv = 1.0f / lrow[rr];
        const int n = q0 + w*16 + g + rr*8;
        #pragma unroll
        for (int nt = 0; nt < 8; nt++) {
            __half2 hh = __floats2half2_rn(o[nt][rr*2] * inv, o[nt][rr*2+1] * inv);
            *(uint32_t*)(g_ah + ((size_t)b*NN + n)*DD + h*DKK + 8*nt + 2*q4) =
                *(uint32_t*)&hh;
        }
    }
}

// ---------------------------------------------------------------------------
extern "C" void kernel_launch(void* const* d_in, const int* in_sizes, int n_in,
                              void* d_out, int out_size)
{
    const float* x    = (const float*)d_in[0];
    const void*  mask = d_in[1];
    const float* Wq   = (const float*)d_in[2];
    const float* bq   = (const float*)d_in[3];
    const float* Wk   = (const float*)d_in[4];
    const float* bk   = (const float*)d_in[5];
    const float* Wv   = (const float*)d_in[6];
    const float* bv   = (const float*)d_in[7];
    const float* Wo   = (const float*)d_in[8];
    const float* bo   = (const float*)d_in[9];
    float* out = (float*)d_out;

    __half *xh, *wh, *ah;
    cudaGetSymbolAddress((void**)&xh, g_xh);
    cudaGetSymbolAddress((void**)&wh, g_wh);
    cudaGetSymbolAddress((void**)&ah, g_ah);

    cvt_all<<<1184, 256>>>((const float4*)x, (const float4*)Wq, (const float4*)Wk,
                           (const float4*)Wv, (const float4*)Wo);

    cudaFuncSetAttribute(gemm_hp<0>, cudaFuncAttributeMaxDynamicSharedMemorySize, G_SMEM);
    cudaFuncSetAttribute(gemm_hp<1>, cudaFuncAttributeMaxDynamicSharedMemorySize, G_SMEM);
    cudaFuncSetAttribute(gemm_hp<2>, cudaFuncAttributeMaxDynamicSharedMemorySize, G_SMEM);
    cudaFuncSetAttribute(gemm_hp<3>, cudaFuncAttributeMaxDynamicSharedMemorySize, G_SMEM);

    dim3 ggrid(BB*NN/128, DD/128);   // 32 x 8
    gemm_hp<0><<<ggrid, 256, G_SMEM>>>(xh, wh + 0*(size_t)DD*DD, bq, nullptr);
    gemm_hp<1><<<ggrid, 256, G_SMEM>>>(xh, wh + 1*(size_t)DD*DD, bk, nullptr);
    gemm_hp<2><<<ggrid, 256, G_SMEM>>>(xh, wh + 2*(size_t)DD*DD, bv, nullptr);

    dim3 agrid(NN/128, HH, BB);      // 8 x 16 x 4
    attn_fwd<<<agrid, 256>>>(mask);

    gemm_hp<3><<<ggrid, 256, G_SMEM>>>(ah, wh + 3*(size_t)DD*DD, bo, out);
}